// round 1
// baseline (speedup 1.0000x reference)
#include <cuda_runtime.h>
#include <cstdint>

// Problem constants (fixed shapes):
//   x: [B=8, W=37, W=37, D=384] fp32, channel-last
//   out: [B, 29*D, W, W] fp32; out(b,bin,c,y,x) at ((b*29+bin)*D + c)*W*W + y*W + x
//   bins 0..8 : raw input shifted by (dy,dx) in {-1,0,1}^2, border-clamped
//   bins 9..16: 3x3 avgpool (count_include_pad=False) shifted by (dy,dx) in {-3,0,3}^2 \ {0,0}
//   bins 17..28: zeros

#define BATCH 8
#define W 37
#define D 384
#define HALFD 192
#define TSTRIDE 193           // 193 mod 32 == 1 -> conflict-free transpose reads
#define NBINS 29
#define PLANE (W * W)         // 1369
#define CHPLANE ((size_t)D * PLANE)  // 525696 floats per (b,bin)

// Scratch for pooled input, same layout as input (channel-last). 16.8 MB.
__device__ float g_pool[BATCH * W * W * D];

// Shift tables for the 17 filled bins (order matches the reference nested loops).
__device__ __constant__ int8_t c_dy[17] = {-1,-1,-1, 0,0,0, 1,1,1,  -3,-3,-3, 0,0, 3,3,3};
__device__ __constant__ int8_t c_dx[17] = {-1, 0, 1,-1,0,1,-1,0,1,  -3, 0, 3,-3,3,-3,0,3};

// ---------------------------------------------------------------------------
// Kernel 1: 3x3 average pool, stride 1, count_include_pad=False.
// One thread per float4 of channels. Fully coalesced reads/writes.
// ---------------------------------------------------------------------------
__global__ void pool3_kernel(const float* __restrict__ in) {
    const int D4 = D / 4;                      // 96
    int idx = blockIdx.x * blockDim.x + threadIdx.x;
    const int total = BATCH * W * W * D4;
    if (idx >= total) return;

    int c4 = idx % D4;
    int t  = idx / D4;
    int x  = t % W; t /= W;
    int y  = t % W;
    int b  = t / W;

    int y0 = max(y - 1, 0), y1 = min(y + 1, W - 1);
    int x0 = max(x - 1, 0), x1 = min(x + 1, W - 1);

    const float4* inp = reinterpret_cast<const float4*>(in);
    float4 s = make_float4(0.f, 0.f, 0.f, 0.f);
    for (int yi = y0; yi <= y1; yi++) {
        for (int xi = x0; xi <= x1; xi++) {
            float4 v = inp[(size_t)((b * W + yi) * W + xi) * D4 + c4];
            s.x += v.x; s.y += v.y; s.z += v.z; s.w += v.w;
        }
    }
    float inv = 1.0f / (float)((y1 - y0 + 1) * (x1 - x0 + 1));
    s.x *= inv; s.y *= inv; s.z *= inv; s.w *= inv;
    reinterpret_cast<float4*>(g_pool)[idx] = s;
}

// ---------------------------------------------------------------------------
// Kernel 2: zero-fill bins 17..28 for every batch. float4 stores.
// Per batch: start float4 = (b*29+17) * (CHPLANE/4), length 12 * CHPLANE/4.
// CHPLANE = 525696 is divisible by 4, so all regions are 16B aligned.
// ---------------------------------------------------------------------------
__global__ void zero_kernel(float4* __restrict__ out4) {
    const size_t plane4 = CHPLANE / 4;             // 131424
    const size_t len4   = 12 * plane4;             // per batch
    size_t idx = (size_t)blockIdx.x * blockDim.x + threadIdx.x;
    const size_t total = (size_t)BATCH * len4;
    if (idx >= total) return;
    size_t b = idx / len4;
    size_t r = idx - b * len4;
    out4[(b * NBINS + 17) * plane4 + r] = make_float4(0.f, 0.f, 0.f, 0.f);
}

// ---------------------------------------------------------------------------
// Kernel 3: gather + transpose.
// Block = (b, bin, y). For each c-half (192 channels):
//   load tile[x][c] = srcrow[clamp(x+dx)*D + c]   (coalesced over c)
//   store out[...,(c0+c)*PLANE + y*W + x] = tile[x][c]  (coalesced over x)
// smem tile padded to stride 193 -> transpose reads are bank-conflict-free.
// ---------------------------------------------------------------------------
__global__ __launch_bounds__(256) void gather_kernel(const float* __restrict__ in,
                                                     float* __restrict__ out) {
    __shared__ float tile[W * TSTRIDE];  // 37*193*4 = 28564 B

    const int y   = blockIdx.x;
    const int bin = blockIdx.y;
    const int b   = blockIdx.z;

    const int dy = c_dy[bin];
    const int dx = c_dx[bin];
    const int yy = min(max(y + dy, 0), W - 1);

    const float* src = (bin < 9) ? in : g_pool;
    const float* srcrow = src + (size_t)((b * W + yy) * W) * D;

    float* outbase = out + ((size_t)(b * NBINS + bin)) * CHPLANE + (size_t)y * W;

    #pragma unroll
    for (int pass = 0; pass < 2; pass++) {
        const int c0 = pass * HALFD;

        // Load phase: consecutive threads -> consecutive channels (coalesced).
        for (int idx = threadIdx.x; idx < W * HALFD; idx += 256) {
            int x = idx / HALFD;
            int c = idx - x * HALFD;
            int xx = min(max(x + dx, 0), W - 1);
            tile[x * TSTRIDE + c] = srcrow[(size_t)xx * D + c0 + c];
        }
        __syncthreads();

        // Store phase: consecutive threads -> consecutive x (coalesced rows of 37).
        for (int idx = threadIdx.x; idx < W * HALFD; idx += 256) {
            int c = idx / W;
            int x = idx - c * W;
            outbase[(size_t)(c0 + c) * PLANE + x] = tile[x * TSTRIDE + c];
        }
        __syncthreads();
    }
}

// ---------------------------------------------------------------------------
extern "C" void kernel_launch(void* const* d_in, const int* in_sizes, int n_in,
                              void* d_out, int out_size) {
    const float* x = (const float*)d_in[0];
    float* out = (float*)d_out;

    // 1) pool
    {
        int total = BATCH * W * W * (D / 4);
        int threads = 256;
        int blocks = (total + threads - 1) / threads;
        pool3_kernel<<<blocks, threads>>>(x);
    }
    // 2) zeros (independent of pool; same stream keeps it ordered anyway)
    {
        size_t total = (size_t)BATCH * 12 * (CHPLANE / 4);
        int threads = 256;
        int blocks = (int)((total + threads - 1) / threads);
        zero_kernel<<<blocks, threads>>>((float4*)out);
    }
    // 3) gather/transpose for the 17 filled bins
    {
        dim3 grid(W, 17, BATCH);
        gather_kernel<<<grid, 256>>>(x, out);
    }
}

// round 2
// speedup vs baseline: 1.3374x; 1.3374x over previous
#include <cuda_runtime.h>
#include <cstdint>

// Shapes (fixed):
//   x:   [B=8, W=37, W=37, D=384] fp32, channel-last
//   out: [B, 29*D, W, W] fp32; out(b,bin,c,y,x) at ((b*29+bin)*D + c)*PLANE + y*W + x
//   bins 0..8 : raw input shifted by (dy,dx) in {-1,0,1}^2 (row-major order), clamped
//   bins 9..16: 3x3 avgpool (count_include_pad=False) shifted by (dy,dx) in {-3,0,3}^2 \ {0,0}
//   bins 17..28: zeros

#define BATCH 8
#define W 37
#define D 384
#define HALFD 192
#define TSTRIDE 193            // 193 mod 32 == 1 -> conflict-free smem transpose
#define NBINS 29
#define PLANE (W * W)          // 1369
#define CHPLANE ((size_t)D * PLANE)

// Planar copy of the input: [b, c, y*W+x]. 16.8 MB.
__device__ float g_tin[(size_t)BATCH * D * PLANE];

// ---------------------------------------------------------------------------
// Kernel 1: channel-last -> planar transpose via padded smem tile.
// Block = (y, half, b). Loads coalesced over c, stores coalesced over x.
// ---------------------------------------------------------------------------
__global__ __launch_bounds__(256) void transpose_kernel(const float* __restrict__ in) {
    __shared__ float tile[W * TSTRIDE];   // 28564 B

    const int y    = blockIdx.x;
    const int half = blockIdx.y;          // 0 or 1 (192 channels each)
    const int b    = blockIdx.z;
    const int c0   = half * HALFD;

    const float* srcrow = in + ((size_t)(b * W + y) * W) * D + c0;

    for (int idx = threadIdx.x; idx < W * HALFD; idx += 256) {
        int x = idx / HALFD;
        int c = idx - x * HALFD;
        tile[x * TSTRIDE + c] = srcrow[(size_t)x * D + c];
    }
    __syncthreads();

    for (int idx = threadIdx.x; idx < W * HALFD; idx += 256) {
        int c = idx / W;
        int x = idx - c * W;
        g_tin[((size_t)b * D + c0 + c) * PLANE + y * W + x] = tile[x * TSTRIDE + c];
    }
}

// ---------------------------------------------------------------------------
// Kernel 2: fanout. Block = (c, b). Loads one plane into smem, pools it in
// smem, then writes all 29 output planes for this (b, c) with coalesced
// scalar stores (threads = consecutive i within a plane).
// ---------------------------------------------------------------------------
__global__ __launch_bounds__(256) void fanout_kernel(float* __restrict__ out) {
    __shared__ float s_raw[PLANE];
    __shared__ float s_pool[PLANE];

    const int c = blockIdx.x;
    const int b = blockIdx.y;

    const float* tin = g_tin + ((size_t)b * D + c) * PLANE;

    // Load raw plane (coalesced; L2-resident after transpose kernel).
    for (int i = threadIdx.x; i < PLANE; i += 256)
        s_raw[i] = tin[i];
    __syncthreads();

    // 3x3 avg pool (count_include_pad=False) entirely in smem.
    for (int i = threadIdx.x; i < PLANE; i += 256) {
        int y = i / W;
        int x = i - y * W;
        int y0 = max(y - 1, 0), y1 = min(y + 1, W - 1);
        int x0 = max(x - 1, 0), x1 = min(x + 1, W - 1);
        float s = 0.f;
        for (int yi = y0; yi <= y1; yi++)
            for (int xi = x0; xi <= x1; xi++)
                s += s_raw[yi * W + xi];
        s_pool[i] = s * (1.0f / (float)((y1 - y0 + 1) * (x1 - x0 + 1)));
    }
    __syncthreads();

    float* obase = out + ((size_t)(b * NBINS) * D + c) * PLANE;

    for (int i = threadIdx.x; i < PLANE; i += 256) {
        int y = i / W;
        int x = i - y * W;

        // Clamped neighbor coordinates.
        int ym1 = max(y - 1, 0) * W, yp1 = min(y + 1, W - 1) * W;
        int ym3 = max(y - 3, 0) * W, yp3 = min(y + 3, W - 1) * W;
        int yc  = y * W;
        int xm1 = max(x - 1, 0), xp1 = min(x + 1, W - 1);
        int xm3 = max(x - 3, 0), xp3 = min(x + 3, W - 1);

        float v[17];
        // k=0 bins: raw, (dy,dx) row-major over {-1,0,1}^2
        v[0]  = s_raw[ym1 + xm1];  v[1]  = s_raw[ym1 + x];   v[2]  = s_raw[ym1 + xp1];
        v[3]  = s_raw[yc  + xm1];  v[4]  = s_raw[i];         v[5]  = s_raw[yc  + xp1];
        v[6]  = s_raw[yp1 + xm1];  v[7]  = s_raw[yp1 + x];   v[8]  = s_raw[yp1 + xp1];
        // k=1 bins: pooled, (dy,dx) over {-3,0,3}^2 minus (0,0)
        v[9]  = s_pool[ym3 + xm3]; v[10] = s_pool[ym3 + x];  v[11] = s_pool[ym3 + xp3];
        v[12] = s_pool[yc  + xm3]; v[13] = s_pool[yc  + xp3];
        v[14] = s_pool[yp3 + xm3]; v[15] = s_pool[yp3 + x];  v[16] = s_pool[yp3 + xp3];

        float* o = obase + i;
        #pragma unroll
        for (int bin = 0; bin < 17; bin++)
            o[(size_t)bin * CHPLANE] = v[bin];
        #pragma unroll
        for (int bin = 17; bin < NBINS; bin++)
            o[(size_t)bin * CHPLANE] = 0.f;
    }
}

// ---------------------------------------------------------------------------
extern "C" void kernel_launch(void* const* d_in, const int* in_sizes, int n_in,
                              void* d_out, int out_size) {
    const float* x = (const float*)d_in[0];
    float* out = (float*)d_out;

    {
        dim3 grid(W, 2, BATCH);   // 592 blocks
        transpose_kernel<<<grid, 256>>>(x);
    }
    {
        dim3 grid(D, BATCH);      // 3072 blocks
        fanout_kernel<<<grid, 256>>>(out);
    }
}

// round 3
// speedup vs baseline: 1.5360x; 1.1485x over previous
#include <cuda_runtime.h>
#include <cstdint>

// Shapes (fixed):
//   x:   [B=8, 37, 37, 384] fp32, channel-last
//   out: [B, 29*384, 37, 37] fp32; out(b,bin,c,y,x) at ((b*29+bin)*384 + c)*1369 + y*37 + x
//   bins 0..8 : raw shifted by (dy,dx) in {-1,0,1}^2 (row-major), border-clamped
//   bins 9..16: 3x3 avgpool (count_include_pad=False) shifted by (dy,dx) in {-3,0,3}^2 \ {0,0}
//   bins 17..28: zeros

#define BATCH 8
#define W 37
#define D 384
#define NBINS 29
#define PLANE (W * W)                    // 1369
#define CHPLANE ((size_t)D * PLANE)      // 525696
#define SWZ(j) ((j) + ((j) >> 5))        // pad-1-per-32: stride-4 lane access -> conflict-free
#define SSZ (PLANE + (PLANE >> 5) + 2)   // 1412+

__device__ __forceinline__ int clampw(int v) { return min(max(v, 0), W - 1); }

// Gather one value with border clamp from a swizzled smem plane.
__device__ __forceinline__ float gat(const float* a, int y, int x) {
    return a[SWZ(clampw(y) * W + clampw(x))];
}

__device__ __constant__ int c_dy[17] = {-1,-1,-1, 0,0,0, 1,1,1,  -3,-3,-3, 0,0, 3,3,3};
__device__ __constant__ int c_dx[17] = {-1, 0, 1,-1,0,1,-1,0,1,  -3, 0, 3,-3,3,-3,0,3};

__global__ __launch_bounds__(256) void fanout_kernel(const float* __restrict__ in,
                                                     float* __restrict__ out) {
    __shared__ float sr[SSZ];   // raw plane   (swizzled)
    __shared__ float sp[SSZ];   // pooled plane (swizzled)

    const int c = blockIdx.x;
    const int b = blockIdx.y;

    // ---- Load this (b,c) plane from channel-last input (L2-resident sectors) ----
    const float* src = in + (size_t)b * PLANE * D + c;
    for (int i = threadIdx.x; i < PLANE; i += 256)
        sr[SWZ(i)] = src[(size_t)i * D];
    __syncthreads();

    // ---- 3x3 avg pool (count_include_pad=False) in smem ----
    for (int i = threadIdx.x; i < PLANE; i += 256) {
        int y = i / W, x = i - y * W;
        int y0 = max(y - 1, 0), y1 = min(y + 1, W - 1);
        int x0 = max(x - 1, 0), x1 = min(x + 1, W - 1);
        float s = 0.f;
        for (int yy = y0; yy <= y1; yy++)
            for (int xx = x0; xx <= x1; xx++)
                s += sr[SWZ(yy * W + xx)];
        sp[SWZ(i)] = s * (1.0f / (float)((y1 - y0 + 1) * (x1 - x0 + 1)));
    }
    __syncthreads();

    // ---- Gather + store all 29 bins ----
    const size_t ob = ((size_t)(b * NBINS) * D + c) * PLANE;
    float* obase = out + ob;
    const int phase = (int)(ob & 3);
    const int head  = (4 - phase) & 3;            // scalar elements before aligned body
    const int nq    = (PLANE - head) >> 2;        // aligned float4 quads
    const int tail  = (PLANE - head) & 3;         // scalar elements after body

    // Body: float4 quads (16B-aligned for every bin since CHPLANE % 4 == 0).
    for (int q = threadIdx.x; q < nq; q += 256) {
        const int i0 = head + 4 * q;
        int y0 = i0 / W, x0 = i0 - y0 * W;
        int ys[4], xs[4];
        #pragma unroll
        for (int e = 0; e < 4; e++) {
            int xi = x0 + e, yi = y0;
            if (xi >= W) { xi -= W; yi++; }       // at most one row crossing (W=37 > 3)
            ys[e] = yi; xs[e] = xi;
        }

        #pragma unroll
        for (int bin = 0; bin < 17; bin++) {
            const float* a = (bin < 9) ? sr : sp;
            const int dy = c_dy[bin], dx = c_dx[bin];
            float4 r;
            r.x = gat(a, ys[0] + dy, xs[0] + dx);
            r.y = gat(a, ys[1] + dy, xs[1] + dx);
            r.z = gat(a, ys[2] + dy, xs[2] + dx);
            r.w = gat(a, ys[3] + dy, xs[3] + dx);
            *reinterpret_cast<float4*>(obase + (size_t)bin * CHPLANE + i0) = r;
        }
        const float4 z = make_float4(0.f, 0.f, 0.f, 0.f);
        #pragma unroll
        for (int bin = 17; bin < NBINS; bin++)
            *reinterpret_cast<float4*>(obase + (size_t)bin * CHPLANE + i0) = z;
    }

    // Head/tail: scalar stores for the few unaligned elements.
    int si = -1;
    if ((int)threadIdx.x < head)
        si = (int)threadIdx.x;                                    // i in [0, head)
    else if ((int)threadIdx.x >= 32 && (int)threadIdx.x < 32 + tail)
        si = head + 4 * nq + ((int)threadIdx.x - 32);             // i in [head+4nq, PLANE)
    if (si >= 0) {
        int y = si / W, x = si - y * W;
        #pragma unroll
        for (int bin = 0; bin < 17; bin++) {
            const float* a = (bin < 9) ? sr : sp;
            obase[(size_t)bin * CHPLANE + si] = gat(a, y + c_dy[bin], x + c_dx[bin]);
        }
        #pragma unroll
        for (int bin = 17; bin < NBINS; bin++)
            obase[(size_t)bin * CHPLANE + si] = 0.f;
    }
}

// ---------------------------------------------------------------------------
extern "C" void kernel_launch(void* const* d_in, const int* in_sizes, int n_in,
                              void* d_out, int out_size) {
    const float* x = (const float*)d_in[0];
    float* out = (float*)d_out;
    dim3 grid(D, BATCH);   // 3072 blocks
    fanout_kernel<<<grid, 256>>>(x, out);
}